// round 16
// baseline (speedup 1.0000x reference)
#include <cuda_runtime.h>
#include <math.h>

#define INSIZE     1024
#define NREFL      40          // 20 U + 20 V, in application order
#define NBLK       8
#define BLKR       5           // reflectors per block
#define BATCH      32768
#define ROWS_PW    4           // rows per warp-PAIR group
#define NBATCH     (BATCH / ROWS_PW)
#define THREADS    320
#define NGRP       (THREADS / 64)   // 5 groups of 2 warps

// Scratch (no device allocs allowed)
__device__ float g_sigma[INSIZE];
__device__ float g_c[NREFL];                 // c_k = 2/||y_k||^2, app order
__device__ float g_G[NBLK][BLKR * BLKR];     // Gs[m][j] = c_j * (y_m . y_j), m<j
__device__ unsigned int g_work;

typedef unsigned long long ull;

// Packed fp32x2 FMA (Blackwell FFMA2).
__device__ __forceinline__ ull ffma2(ull a, ull b, ull c) {
    ull d;
    asm("fma.rn.f32x2 %0, %1, %2, %3;" : "=l"(d) : "l"(a), "l"(b), "l"(c));
    return d;
}

__device__ __forceinline__ void gbar(int id) {
    asm volatile("bar.sync %0, %1;" :: "r"(id), "r"(64) : "memory");
}

union F4U {
    float4 f;
    ull p[2];
    float s[4];
};

union U2 {
    ull u;
    float f[2];
};

// Reflector row k (application order) -> source pointer.
// k 0..19 : U row k.   k 20..39 : V row (39-k)  (V applied 19 .. 0).
__device__ __forceinline__ const float* yrow(int k, const float* U,
                                             const float* V) {
    return (k < 20) ? (U + (size_t)k * INSIZE)
                    : (V + (size_t)(39 - k) * INSIZE);
}

// ---------------------------------------------------------------------------
// Prep: sigma, c_k, scaled Gram per block, reset work queue.  1024 threads.
// ---------------------------------------------------------------------------
__global__ void prep_kernel(const float* __restrict__ U,
                            const float* __restrict__ p,
                            const float* __restrict__ V) {
    __shared__ float sc[NREFL];          // c_k, application order

    const int tid  = threadIdx.x;
    const int w    = tid >> 5;
    const int lane = tid & 31;

    if (tid == 0) g_work = 0u;

    if (tid < INSIZE) {
        float pv = p[tid];
        float s = 1.0f / (1.0f + expf(-pv));
        g_sigma[tid] = 0.4f * s + 0.6f;  // 2R(sigmoid-0.5)+mean, R=0.2
    }

    // Norms: warp w (<20) handles U row w (app idx w) and V row w (app 39-w).
    if (w < 20) {
        float su = 0.0f, sv = 0.0f;
        for (int j = lane; j < INSIZE; j += 32) {
            float uu = U[(size_t)w * INSIZE + j]; su += uu * uu;
            float vv = V[(size_t)w * INSIZE + j]; sv += vv * vv;
        }
        #pragma unroll
        for (int off = 16; off; off >>= 1) {
            su += __shfl_xor_sync(0xffffffffu, su, off);
            sv += __shfl_xor_sync(0xffffffffu, sv, off);
        }
        if (lane == 0) {
            sc[w]      = 2.0f / su;
            sc[39 - w] = 2.0f / sv;
        }
    }
    __syncthreads();

    if (tid < NREFL) g_c[tid] = sc[tid];

    // Scaled Gram: flat space of NBLK*25 slots (b, m, j); only m < j computed.
    for (int pid = w; pid < NBLK * BLKR * BLKR; pid += 32) {
        int b   = pid / (BLKR * BLKR);
        int rem = pid % (BLKR * BLKR);
        int m   = rem / BLKR;
        int j   = rem % BLKR;
        if (m >= j) continue;
        const float* ym = yrow(b * BLKR + m, U, V);
        const float* yj = yrow(b * BLKR + j, U, V);
        float s = 0.0f;
        for (int e = lane; e < INSIZE; e += 32) s += ym[e] * yj[e];
        #pragma unroll
        for (int off = 16; off; off >>= 1)
            s += __shfl_xor_sync(0xffffffffu, s, off);
        if (lane == 0) g_G[b][rem] = s * sc[b * BLKR + j];
    }
}

// ---------------------------------------------------------------------------
// Main: persistent, 1 CTA/SM, 5 groups x (2 warps, 4 rows), blocked apply.
// Each thread owns 4 float4 of each row: column float4 index g + 64*j.
// ---------------------------------------------------------------------------
extern __shared__ float smem[];

// Apply one block of 5 reflectors to 4 rows split across a warp pair.
__device__ __forceinline__ void block_apply(F4U xr[ROWS_PW][4],
                                            const float* __restrict__ sYb,
                                            const float* __restrict__ sGb,
                                            const float* __restrict__ sCb,
                                            float* __restrict__ sP,
                                            int h, int g, int par, int barid) {
    const int lane = g & 31;

    // ---- dots: acc[r][c] over this thread's 16 columns ----
    ull acc[ROWS_PW][BLKR];
    #pragma unroll
    for (int r = 0; r < ROWS_PW; r++)
        #pragma unroll
        for (int c = 0; c < BLKR; c++) acc[r][c] = 0ull;

    #pragma unroll
    for (int j = 0; j < 4; j++) {
        F4U y[BLKR];
        #pragma unroll
        for (int c = 0; c < BLKR; c++)
            y[c].f = reinterpret_cast<const float4*>(sYb + c * INSIZE)
                         [g + 64 * j];
        #pragma unroll
        for (int c = 0; c < BLKR; c++) {
            #pragma unroll
            for (int r = 0; r < ROWS_PW; r++) {
                acc[r][c] = ffma2(xr[r][j].p[0], y[c].p[0], acc[r][c]);
                acc[r][c] = ffma2(xr[r][j].p[1], y[c].p[1], acc[r][c]);
            }
        }
    }

    float d[ROWS_PW][BLKR];
    #pragma unroll
    for (int r = 0; r < ROWS_PW; r++)
        #pragma unroll
        for (int c = 0; c < BLKR; c++) {
            U2 t; t.u = acc[r][c];
            d[r][c] = t.f[0] + t.f[1];
        }

    // ---- intra-warp butterfly: 20 independent shuffles per stage ----
    #pragma unroll
    for (int off = 16; off; off >>= 1) {
        #pragma unroll
        for (int r = 0; r < ROWS_PW; r++)
            #pragma unroll
            for (int c = 0; c < BLKR; c++)
                d[r][c] += __shfl_xor_sync(0xffffffffu, d[r][c], off);
    }

    // ---- cross-warp combine via smem (parity double-buffered) ----
    float* buf = sP + par * 2 * 20;     // [h][20]
    if (lane == 0) {
        #pragma unroll
        for (int r = 0; r < ROWS_PW; r++)
            #pragma unroll
            for (int c = 0; c < BLKR; c++)
                buf[h * 20 + r * BLKR + c] = d[r][c];
    }
    gbar(barid);
    {
        const float* ob = buf + (1 - h) * 20;
        #pragma unroll
        for (int r = 0; r < ROWS_PW; r++)
            #pragma unroll
            for (int c = 0; c < BLKR; c++)
                d[r][c] += ob[r * BLKR + c];
    }

    // ---- forward substitution (exact sequential algorithm, dots hoisted):
    //      s_j = c_j * d_j - sum_{m<j} Gs[m][j] * s_m,  Gs pre-scaled by c_j.
    #pragma unroll
    for (int j = 0; j < BLKR; j++) {
        const float cj = sCb[j];
        float a0 = cj * d[0][j];
        float a1 = cj * d[1][j];
        float a2 = cj * d[2][j];
        float a3 = cj * d[3][j];
        #pragma unroll
        for (int m = 0; m < j; m++) {
            const float g2 = sGb[m * BLKR + j];
            a0 -= g2 * d[0][m];
            a1 -= g2 * d[1][m];
            a2 -= g2 * d[2][m];
            a3 -= g2 * d[3][m];
        }
        d[0][j] = a0; d[1][j] = a1; d[2][j] = a2; d[3][j] = a3;
    }

    // ---- pack -s into broadcast pairs (d dies here) ----
    ull ns[ROWS_PW][BLKR];
    #pragma unroll
    for (int r = 0; r < ROWS_PW; r++)
        #pragma unroll
        for (int c = 0; c < BLKR; c++) {
            U2 t; t.f[0] = -d[r][c]; t.f[1] = t.f[0];
            ns[r][c] = t.u;
        }

    // ---- axpy sweep: xr -= s_c * y_c ----
    #pragma unroll
    for (int j = 0; j < 4; j++) {
        F4U y[BLKR];
        #pragma unroll
        for (int c = 0; c < BLKR; c++)
            y[c].f = reinterpret_cast<const float4*>(sYb + c * INSIZE)
                         [g + 64 * j];
        #pragma unroll
        for (int c = 0; c < BLKR; c++) {
            #pragma unroll
            for (int r = 0; r < ROWS_PW; r++) {
                xr[r][j].p[0] = ffma2(y[c].p[0], ns[r][c], xr[r][j].p[0]);
                xr[r][j].p[1] = ffma2(y[c].p[1], ns[r][c], xr[r][j].p[1]);
            }
        }
    }
}

__global__ void __launch_bounds__(THREADS, 1)
spectral_kernel(const float* __restrict__ x,
                const float* __restrict__ U,
                const float* __restrict__ V,
                const float* __restrict__ bias,
                float* __restrict__ out) {
    float* sY    = smem;                          // 40*1024
    float* sSig  = sY + NREFL * INSIZE;           // 1024
    float* sBias = sSig + INSIZE;                 // 1024
    float* sG    = sBias + INSIZE;                // 200
    float* sC    = sG + NBLK * BLKR * BLKR;       // 40
    float* sPart = sC + NREFL;                    // NGRP * 2par * 2h * 20
    unsigned int* sB = (unsigned int*)(sPart + NGRP * 80);   // NGRP

    const int tid = threadIdx.x;

    // Stage reflectors in application order (V rows reversed).
    for (int idx = tid; idx < NREFL * (INSIZE / 4); idx += THREADS) {
        int row = idx >> 8;              // 256 float4 per row
        int c4  = idx & 255;
        const float4* src = reinterpret_cast<const float4*>(yrow(row, U, V));
        reinterpret_cast<float4*>(sY)[idx] = src[c4];
    }
    for (int i = tid; i < 256; i += THREADS) {
        reinterpret_cast<float4*>(sSig)[i]  =
            reinterpret_cast<const float4*>(g_sigma)[i];
        reinterpret_cast<float4*>(sBias)[i] =
            reinterpret_cast<const float4*>(bias)[i];
    }
    for (int i = tid; i < NBLK * BLKR * BLKR; i += THREADS)
        sG[i] = (&g_G[0][0])[i];
    if (tid < NREFL) sC[tid] = g_c[tid];
    __syncthreads();

    const int grp   = tid >> 6;          // 0..NGRP-1
    const int g     = tid & 63;          // lane within group
    const int h     = (tid >> 5) & 1;    // which warp of the pair
    const int barid = grp + 1;           // named barrier id (1..NGRP)
    float* sP = sPart + grp * 80;

    for (;;) {
        if (g == 0) sB[grp] = atomicAdd(&g_work, 1u);
        gbar(barid);
        unsigned int b = sB[grp];
        if (b >= NBATCH) break;

        const int row0 = (int)b * ROWS_PW;

        F4U xr[ROWS_PW][4];
        #pragma unroll
        for (int r = 0; r < ROWS_PW; r++) {
            const float4* xp =
                reinterpret_cast<const float4*>(x + (size_t)(row0 + r) * INSIZE);
            #pragma unroll
            for (int j = 0; j < 4; j++) xr[r][j].f = xp[g + 64 * j];
        }

        #pragma unroll 1
        for (int blk = 0; blk < NBLK; blk++) {
            if (blk == NBLK / 2) {
                // diagonal sigma between U and V phases
                const float4* sp = reinterpret_cast<const float4*>(sSig);
                #pragma unroll
                for (int j = 0; j < 4; j++) {
                    float4 sg = sp[g + 64 * j];
                    #pragma unroll
                    for (int r = 0; r < ROWS_PW; r++) {
                        xr[r][j].s[0] *= sg.x; xr[r][j].s[1] *= sg.y;
                        xr[r][j].s[2] *= sg.z; xr[r][j].s[3] *= sg.w;
                    }
                }
            }
            block_apply(xr, sY + (size_t)blk * BLKR * INSIZE,
                        sG + blk * BLKR * BLKR, sC + blk * BLKR,
                        sP, h, g, blk & 1, barid);
        }

        // bias add + store
        #pragma unroll
        for (int r = 0; r < ROWS_PW; r++) {
            float4* op =
                reinterpret_cast<float4*>(out + (size_t)(row0 + r) * INSIZE);
            const float4* bp = reinterpret_cast<const float4*>(sBias);
            #pragma unroll
            for (int j = 0; j < 4; j++) {
                float4 v = xr[r][j].f;
                float4 bb = bp[g + 64 * j];
                v.x += bb.x; v.y += bb.y; v.z += bb.z; v.w += bb.w;
                op[g + 64 * j] = v;
            }
        }
    }
}

// ---------------------------------------------------------------------------
extern "C" void kernel_launch(void* const* d_in, const int* in_sizes, int n_in,
                              void* d_out, int out_size) {
    const float* x    = (const float*)d_in[0];
    const float* U    = (const float*)d_in[1];
    const float* p    = (const float*)d_in[2];
    const float* V    = (const float*)d_in[3];
    const float* bias = (const float*)d_in[4];
    float* out = (float*)d_out;

    (void)in_sizes; (void)n_in; (void)out_size;

    prep_kernel<<<1, 1024>>>(U, p, V);

    int nsm = 148;
    cudaDeviceGetAttribute(&nsm, cudaDevAttrMultiProcessorCount, 0);

    size_t smem_bytes =
        (size_t)(NREFL * INSIZE + 2 * INSIZE + NBLK * BLKR * BLKR + NREFL +
                 NGRP * 80) * sizeof(float) + NGRP * sizeof(unsigned int);
    cudaFuncSetAttribute(spectral_kernel,
                         cudaFuncAttributeMaxDynamicSharedMemorySize,
                         (int)smem_bytes);

    spectral_kernel<<<nsm, THREADS, smem_bytes>>>(x, U, V, bias, out);
}

// round 17
// speedup vs baseline: 1.2330x; 1.2330x over previous
#include <cuda_runtime.h>
#include <math.h>

#define INSIZE     1024
#define NREFL      20
#define BATCH      32768
#define ROWS_PW    4
#define NBATCH     (BATCH / ROWS_PW)   // 8192 batches of 4 rows
#define THREADS    320                 // 10 warps @ <=204 regs

// Scratch (no device allocs allowed)
__device__ float g_sigma[INSIZE];
__device__ float g_cu[NREFL];
__device__ float g_cv[NREFL];
__device__ unsigned int g_work;

typedef unsigned long long ull;

// Packed fp32x2 FMA (Blackwell FFMA2) — one instruction, two fp32 FMAs.
__device__ __forceinline__ ull ffma2(ull a, ull b, ull c) {
    ull d;
    asm("fma.rn.f32x2 %0, %1, %2, %3;" : "=l"(d) : "l"(a), "l"(b), "l"(c));
    return d;
}

union F4U {
    float4 f;
    ull p[2];
    float s[4];
};

// ---------------------------------------------------------------------------
// Prep: sigma diagonal from p, 2/||u||^2 per reflector, reset work queue.
// ---------------------------------------------------------------------------
__global__ void prep_kernel(const float* __restrict__ U,
                            const float* __restrict__ p,
                            const float* __restrict__ V) {
    int tid = threadIdx.x;                 // launched with 1024 threads
    if (tid == 0) g_work = 0u;
    if (tid < INSIZE) {
        float pv = p[tid];
        float s = 1.0f / (1.0f + expf(-pv));
        // 2*R*(sigmoid-0.5)+SIGMA_MEAN with R=0.2, SIGMA_MEAN=0.8
        g_sigma[tid] = 0.4f * s + 0.6f;
    }
    int w = tid >> 5;
    int lane = tid & 31;
    if (w < NREFL) {
        float su = 0.0f, sv = 0.0f;
        for (int j = lane; j < INSIZE; j += 32) {
            float uu = U[w * INSIZE + j]; su += uu * uu;
            float vv = V[w * INSIZE + j]; sv += vv * vv;
        }
        #pragma unroll
        for (int off = 16; off; off >>= 1) {
            su += __shfl_xor_sync(0xffffffffu, su, off);
            sv += __shfl_xor_sync(0xffffffffu, sv, off);
        }
        if (lane == 0) {
            g_cu[w] = 2.0f / su;
            g_cv[w] = 2.0f / sv;
        }
    }
}

// ---------------------------------------------------------------------------
// Main: persistent, 1 CTA/SM, rows resident in registers, reflectors in smem.
// Single y-fragment load per reflector serves BOTH dot and axpy.
// ---------------------------------------------------------------------------
extern __shared__ float smem[];

// Apply one reflector (fragment in uf, scale c) to 4 register-resident rows.
// Dot chains interleaved across rows (8 independent FFMA2 chains), reduce via
// stage-major butterfly (4 independent SHFLs per stage).
__device__ __forceinline__ void reflect4(F4U xr[ROWS_PW][8], const F4U uf[8],
                                         float c) {
    ull a0[ROWS_PW], a1[ROWS_PW];
    #pragma unroll
    for (int r = 0; r < ROWS_PW; r++) { a0[r] = 0ull; a1[r] = 0ull; }
    #pragma unroll
    for (int j = 0; j < 8; j++) {
        #pragma unroll
        for (int r = 0; r < ROWS_PW; r++) {
            a0[r] = ffma2(xr[r][j].p[0], uf[j].p[0], a0[r]);
            a1[r] = ffma2(xr[r][j].p[1], uf[j].p[1], a1[r]);
        }
    }
    float d[ROWS_PW];
    #pragma unroll
    for (int r = 0; r < ROWS_PW; r++) {
        F4U t; t.p[0] = a0[r]; t.p[1] = a1[r];
        d[r] = (t.s[0] + t.s[2]) + (t.s[1] + t.s[3]);
    }
    // Stage-major butterfly: 4 independent shuffles in flight per stage.
    #pragma unroll
    for (int off = 16; off; off >>= 1) {
        float e[ROWS_PW];
        #pragma unroll
        for (int r = 0; r < ROWS_PW; r++)
            e[r] = __shfl_xor_sync(0xffffffffu, d[r], off);
        #pragma unroll
        for (int r = 0; r < ROWS_PW; r++) d[r] += e[r];
    }
    #pragma unroll
    for (int r = 0; r < ROWS_PW; r++) {
        F4U na; na.s[0] = -c * d[r]; na.s[1] = na.s[0];
        #pragma unroll
        for (int j = 0; j < 8; j++) {
            xr[r][j].p[0] = ffma2(uf[j].p[0], na.p[0], xr[r][j].p[0]);
            xr[r][j].p[1] = ffma2(uf[j].p[1], na.p[0], xr[r][j].p[1]);
        }
    }
}

__global__ void __launch_bounds__(THREADS, 1)
spectral_kernel(const float* __restrict__ x,
                const float* __restrict__ U,
                const float* __restrict__ V,
                const float* __restrict__ bias,
                float* __restrict__ out) {
    float* sU    = smem;                      // 20*1024
    float* sV    = sU + NREFL * INSIZE;       // 20*1024
    float* sSig  = sV + NREFL * INSIZE;       // 1024
    float* sBias = sSig + INSIZE;             // 1024
    float* sCu   = sBias + INSIZE;            // 20
    float* sCv   = sCu + NREFL;               // 20

    const int tid = threadIdx.x;

    // Stage reflectors + sigma + bias (float4 copies)
    for (int i = tid; i < NREFL * INSIZE / 4; i += THREADS) {
        reinterpret_cast<float4*>(sU)[i] = reinterpret_cast<const float4*>(U)[i];
        reinterpret_cast<float4*>(sV)[i] = reinterpret_cast<const float4*>(V)[i];
    }
    if (tid < 256) {
        reinterpret_cast<float4*>(sSig)[tid]  = reinterpret_cast<const float4*>(g_sigma)[tid];
        reinterpret_cast<float4*>(sBias)[tid] = reinterpret_cast<const float4*>(bias)[tid];
    }
    if (tid < NREFL) { sCu[tid] = g_cu[tid]; sCv[tid] = g_cv[tid]; }
    __syncthreads();

    const int lane = tid & 31;

    for (;;) {
        // Warp-level atomic work queue (balanced tail).
        unsigned int b;
        if (lane == 0) b = atomicAdd(&g_work, 1u);
        b = __shfl_sync(0xffffffffu, b, 0);
        if (b >= NBATCH) break;

        const int row0 = (int)b * ROWS_PW;

        // Load 4 rows, lane holds float4 elements {4*lane+128*j .. +3}
        F4U xr[ROWS_PW][8];
        #pragma unroll
        for (int r = 0; r < ROWS_PW; r++) {
            const float4* xp =
                reinterpret_cast<const float4*>(x + (size_t)(row0 + r) * INSIZE);
            #pragma unroll
            for (int j = 0; j < 8; j++) xr[r][j].f = xp[lane + 32 * j];
        }

        // ---- U phase: x <- x * H_0 * H_1 * ... * H_19 ----
        #pragma unroll 1
        for (int i = 0; i < NREFL; i++) {
            F4U uf[8];
            const float4* up = reinterpret_cast<const float4*>(sU + i * INSIZE);
            #pragma unroll
            for (int j = 0; j < 8; j++) uf[j].f = up[lane + 32 * j];
            reflect4(xr, uf, sCu[i]);
        }

        // ---- diagonal sigma scale ----
        {
            const float4* sp = reinterpret_cast<const float4*>(sSig);
            #pragma unroll
            for (int j = 0; j < 8; j++) {
                float4 sg = sp[lane + 32 * j];
                #pragma unroll
                for (int r = 0; r < ROWS_PW; r++) {
                    xr[r][j].s[0] *= sg.x; xr[r][j].s[1] *= sg.y;
                    xr[r][j].s[2] *= sg.z; xr[r][j].s[3] *= sg.w;
                }
            }
        }

        // ---- V phase: x <- x * G_19 * G_18 * ... * G_0 ----
        #pragma unroll 1
        for (int i = NREFL - 1; i >= 0; i--) {
            F4U vf[8];
            const float4* vp = reinterpret_cast<const float4*>(sV + i * INSIZE);
            #pragma unroll
            for (int j = 0; j < 8; j++) vf[j].f = vp[lane + 32 * j];
            reflect4(xr, vf, sCv[i]);
        }

        // ---- bias add + store ----
        #pragma unroll
        for (int r = 0; r < ROWS_PW; r++) {
            float4* op =
                reinterpret_cast<float4*>(out + (size_t)(row0 + r) * INSIZE);
            const float4* bp = reinterpret_cast<const float4*>(sBias);
            #pragma unroll
            for (int j = 0; j < 8; j++) {
                float4 v = xr[r][j].f;
                float4 bb = bp[lane + 32 * j];
                v.x += bb.x; v.y += bb.y; v.z += bb.z; v.w += bb.w;
                op[lane + 32 * j] = v;
            }
        }
    }
}

// ---------------------------------------------------------------------------
extern "C" void kernel_launch(void* const* d_in, const int* in_sizes, int n_in,
                              void* d_out, int out_size) {
    const float* x    = (const float*)d_in[0];
    const float* U    = (const float*)d_in[1];
    const float* p    = (const float*)d_in[2];
    const float* V    = (const float*)d_in[3];
    const float* bias = (const float*)d_in[4];
    float* out = (float*)d_out;

    (void)in_sizes; (void)n_in; (void)out_size;

    prep_kernel<<<1, 1024>>>(U, p, V);

    int nsm = 148;
    cudaDeviceGetAttribute(&nsm, cudaDevAttrMultiProcessorCount, 0);

    size_t smem_bytes =
        (size_t)(2 * NREFL * INSIZE + 2 * INSIZE + 2 * NREFL) * sizeof(float);
    cudaFuncSetAttribute(spectral_kernel,
                         cudaFuncAttributeMaxDynamicSharedMemorySize,
                         (int)smem_bytes);

    spectral_kernel<<<nsm, THREADS, smem_bytes>>>(x, U, V, bias, out);
}